// round 6
// baseline (speedup 1.0000x reference)
#include <cuda_runtime.h>
#include <cuda_bf16.h>
#include <math.h>

// ExactWeightedDTM — images (4,1,64,64) f32 -> dtm (4,64,64) f32.
// R=2 => dists_pow == integer d2; crossing always within d2 <= 256 (verified
// rounds 1/3, rel_err 1.3e-7). Per pixel: walk offsets ascending d2,
// ws += clamp(w, mt - cum, 0)*d2, cum += w, stop at cum >= mt; dtm=sqrt(ws/mt).
//
// Round 5: identical to round 4 except the launch-grid bug is fixed
// (round 4 computed grid.x = 4096/256/64*16 = 0 via integer division;
// the kernel never launched). Grid is now dim3(16, BATCH): 64 rows / 4
// rows-per-block = 16 blocks per batch.

#define H 64
#define W 64
#define NPIX 4096
#define BATCH 4
#define RMAX 16
#define SIDE 33            // 2*RMAX+1
#define D2MAX 256
#define NBIN 257
#define NOFF_CAP 800       // >= 797 entries, padded (pads: doff=0,d2=0)
#define CHUNK 8
#define TPB 256
#define ROWS_PB 4          // pixel rows per block
#define BLOCKS_PER_B (H / ROWS_PB)   // 16
#define TW 96              // tile width  = W + 2*RMAX
#define TH 36              // tile height = ROWS_PB + 2*RMAX
#define NTILE (TH * TW)    // 3456 floats

__global__ void __launch_bounds__(TPB) dtm_kernel(
    const float* __restrict__ img, float* __restrict__ out)
{
    __shared__ float s_tile[NTILE];
    __shared__ int2  s_tab[NOFF_CAP];   // {dy*TW+dx, float_bits(d2)} ascending d2
    __shared__ int   s_bin[NBIN];
    __shared__ float s_wsum[TPB / 32];
    __shared__ int   s_total;

    const int tid = threadIdx.x;
    const int b   = blockIdx.y;
    const float* __restrict__ im = img + b * NPIX;
    const int y0    = blockIdx.x * ROWS_PB;
    const int ybase = y0 - RMAX;

    // ---- mass partial: 4 float4/thread, fixed order (issue loads early) ----
    float s;
    {
        const float4* __restrict__ im4 = reinterpret_cast<const float4*>(im);
        float4 v0 = im4[tid];
        float4 v1 = im4[tid + 256];
        float4 v2 = im4[tid + 512];
        float4 v3 = im4[tid + 768];
        s = (((v0.x + v0.y) + (v0.z + v0.w)) + ((v1.x + v1.y) + (v1.z + v1.w)))
          + (((v2.x + v2.y) + (v2.z + v2.w)) + ((v3.x + v3.y) + (v3.z + v3.w)));
    }

    // ---- zero d2 bins ----
    for (int i = tid; i < NBIN; i += TPB) s_bin[i] = 0;

    // ---- stage zero-padded tile ----
    for (int i = tid; i < NTILE; i += TPB) {
        const int r  = i / TW, c = i % TW;
        const int gy = ybase + r, gx = c - RMAX;
        float v = 0.0f;
        if ((unsigned)gy < (unsigned)H && (unsigned)gx < (unsigned)W)
            v = im[(gy << 6) + gx];
        s_tile[i] = v;
    }
    __syncthreads();                                    // bins zeroed

    // ---- count offsets per d2 bin ----
    for (int i = tid; i < SIDE * SIDE; i += TPB) {
        const int dy = i / SIDE - RMAX, dx = i % SIDE - RMAX;
        const int d2 = dy * dy + dx * dx;
        if (d2 <= D2MAX) atomicAdd(&s_bin[d2], 1);
    }

    // warp mass reduce while atomics land (deterministic fixed pattern)
    #pragma unroll
    for (int o = 16; o > 0; o >>= 1) s += __shfl_xor_sync(0xFFFFFFFFu, s, o);
    if ((tid & 31) == 0) s_wsum[tid >> 5] = s;
    __syncthreads();                                    // counts + warp sums done

    // ---- exclusive scan over 257 bins: warp 0, 9 bins/lane + shfl scan ----
    if (tid < 32) {
        int local[9];
        int sum = 0;
        #pragma unroll
        for (int j = 0; j < 9; j++) {
            const int idx = tid * 9 + j;
            const int v = (idx < NBIN) ? s_bin[idx] : 0;
            local[j] = sum; sum += v;
        }
        int incl = sum;
        #pragma unroll
        for (int off = 1; off < 32; off <<= 1) {
            const int n = __shfl_up_sync(0xFFFFFFFFu, incl, off);
            if (tid >= off) incl += n;
        }
        const int excl = incl - sum;
        #pragma unroll
        for (int j = 0; j < 9; j++) {
            const int idx = tid * 9 + j;
            if (idx < NBIN) s_bin[idx] = excl + local[j];
        }
        if (tid == 31) s_total = incl;
    }
    __syncthreads();                                    // scan done

    // ---- scatter (within-tie order is result-invariant) + pad ----
    for (int i = tid; i < SIDE * SIDE; i += TPB) {
        const int dy = i / SIDE - RMAX, dx = i % SIDE - RMAX;
        const int d2 = dy * dy + dx * dx;
        if (d2 <= D2MAX) {
            const int pos = atomicAdd(&s_bin[d2], 1);
            s_tab[pos] = make_int2(dy * TW + dx, __float_as_int((float)d2));
        }
    }
    for (int i = s_total + tid; i < NOFF_CAP; i += TPB)
        s_tab[i] = make_int2(0, 0);
    __syncthreads();                                    // table + tile ready

    // ---- final mass: every thread sums 8 warp sums, fixed order ----
    float mass = 0.0f;
    #pragma unroll
    for (int wi = 0; wi < TPB / 32; wi++) mass += s_wsum[wi];
    const float mt = 0.01f * mass;

    // ---- walk: LDS-only, chunk fast path ----
    const int p = blockIdx.x * TPB + tid;
    const int y = p >> 6, x = p & 63;
    const int tbase = (y - ybase) * TW + (x + RMAX);

    float cum = 0.0f, ws = 0.0f;
    for (int i0 = 0; i0 < NOFF_CAP; i0 += CHUNK) {
        if (__all_sync(0xFFFFFFFFu, cum >= mt)) break;

        float w[CHUNK], dv[CHUNK];
        #pragma unroll
        for (int j = 0; j < CHUNK; j++) {
            const int2 e = s_tab[i0 + j];              // broadcast LDS.64
            w[j]  = s_tile[tbase + e.x];               // conflict-free LDS.32
            dv[j] = __int_as_float(e.y);
        }

        const float sum = ((w[0] + w[1]) + (w[2] + w[3]))
                        + ((w[4] + w[5]) + (w[6] + w[7]));
        if (cum < mt) {
            if (cum + sum <= mt) {
                // whole chunk unclamped: independent tree
                ws += ((w[0] * dv[0] + w[1] * dv[1]) + (w[2] * dv[2] + w[3] * dv[3]))
                    + ((w[4] * dv[4] + w[5] * dv[5]) + (w[6] * dv[6] + w[7] * dv[7]));
            } else {
                // crossing chunk: exact serial clamp (runs once per thread)
                float c = cum;
                #pragma unroll
                for (int j = 0; j < CHUNK; j++) {
                    const float rem = mt - c;
                    ws += fmaxf(fminf(w[j], rem), 0.0f) * dv[j];
                    c  += w[j];
                }
            }
        }
        cum += sum;
    }

    out[b * NPIX + p] = (mass == 0.0f) ? 0.0f : sqrtf(ws / mt);
}

extern "C" void kernel_launch(void* const* d_in, const int* in_sizes, int n_in,
                              void* d_out, int out_size) {
    const float* img = (const float*)d_in[0];
    float* out = (float*)d_out;
    dtm_kernel<<<dim3(BLOCKS_PER_B, BATCH), TPB>>>(img, out);  // (16, 4)
}

// round 8
// speedup vs baseline: 1.1054x; 1.1054x over previous
#include <cuda_runtime.h>
#include <cuda_bf16.h>
#include <math.h>

// ExactWeightedDTM — images (4,1,64,64) f32 -> dtm (4,64,64) f32.
// R=2 => dists_pow == integer d2; crossing always within d2 <= 256 (verified
// rounds 1/3/5, rel_err ~1.1e-7). Per pixel: walk offsets ascending d2,
// ws += clamp(w, mt - cum, 0)*d2, cum += w, stop at cum >= mt; dtm=sqrt(ws/mt).
//
// Round 7: kill the serialized global->shared staging (rounds 3/5 paid ~14
// back-to-back DRAM latencies in the rolled tile loop). All global loads are
// now issued up-front into register arrays (fully unrolled, MLP~30), stores
// after. Walk uses a plain divergent break (no per-iteration __all_sync).

#define H 64
#define W 64
#define NPIX 4096
#define BATCH 4
#define RMAX 16
#define SIDE 33            // 2*RMAX+1
#define D2MAX 256
#define NBIN 257
#define NOFF_CAP 800       // >= 797 entries, padded (pads: doff=0,d2=0)
#define CHUNK 8
#define TPB 256
#define ROWS_PB 4
#define BLOCKS_PER_B (H / ROWS_PB)   // 16
#define TW 96              // W + 2*RMAX
#define TH 36              // ROWS_PB + 2*RMAX
#define NTILE (TH * TW)    // 3456
#define TILE_IT 14         // ceil(NTILE / TPB)

__global__ void __launch_bounds__(TPB) dtm_kernel(
    const float* __restrict__ img, float* __restrict__ out)
{
    __shared__ float s_tile[NTILE];
    __shared__ int2  s_tab[NOFF_CAP];   // {dy*TW+dx, float_bits(d2)} asc d2
    __shared__ int   s_bin[NBIN];
    __shared__ float s_wsum[TPB / 32];
    __shared__ int   s_total;

    const int tid   = threadIdx.x;
    const int b     = blockIdx.y;
    const float* __restrict__ im = img + b * NPIX;
    const int ybase = blockIdx.x * ROWS_PB - RMAX;

    // ---- issue ALL global loads up front (batched, ~30 in flight) ----
    float4 m0, m1, m2, m3;
    {
        const float4* __restrict__ im4 = reinterpret_cast<const float4*>(im);
        m0 = im4[tid];       m1 = im4[tid + 256];
        m2 = im4[tid + 512]; m3 = im4[tid + 768];
    }
    float tv[TILE_IT];
    #pragma unroll
    for (int k = 0; k < TILE_IT; k++) {
        const int i  = tid + k * TPB;
        const int r  = i / TW, c = i % TW;
        const int gy = ybase + r, gx = c - RMAX;
        const bool ok = (i < NTILE)
                      & ((unsigned)gy < (unsigned)H)
                      & ((unsigned)gx < (unsigned)W);
        tv[k] = ok ? __ldg(im + (gy << 6) + gx) : 0.0f;
    }

    // ---- zero bins while loads fly ----
    #pragma unroll
    for (int i = tid; i < NBIN; i += TPB) s_bin[i] = 0;
    __syncthreads();                               // bins zeroed

    // ---- count offsets per d2 bin (overlaps global latency) ----
    #pragma unroll
    for (int k = 0; k < 5; k++) {
        const int i = tid + k * TPB;
        if (i < SIDE * SIDE) {
            const int dy = i / SIDE - RMAX, dx = i % SIDE - RMAX;
            const int d2 = dy * dy + dx * dx;
            if (d2 <= D2MAX) atomicAdd(&s_bin[d2], 1);
        }
    }

    // ---- mass partial: consumes m0..m3, fixed deterministic order ----
    float s = (((m0.x + m0.y) + (m0.z + m0.w)) + ((m1.x + m1.y) + (m1.z + m1.w)))
            + (((m2.x + m2.y) + (m2.z + m2.w)) + ((m3.x + m3.y) + (m3.z + m3.w)));
    #pragma unroll
    for (int o = 16; o > 0; o >>= 1) s += __shfl_xor_sync(0xFFFFFFFFu, s, o);
    if ((tid & 31) == 0) s_wsum[tid >> 5] = s;

    // ---- store tile (consumes tv[], batched stores) ----
    #pragma unroll
    for (int k = 0; k < TILE_IT; k++) {
        const int i = tid + k * TPB;
        if (i < NTILE) s_tile[i] = tv[k];
    }
    __syncthreads();                               // counts + wsum + tile

    // ---- exclusive scan over 257 bins: warp 0, 9 bins/lane + shfl ----
    if (tid < 32) {
        int local[9];
        int sum = 0;
        #pragma unroll
        for (int j = 0; j < 9; j++) {
            const int idx = tid * 9 + j;
            const int v = (idx < NBIN) ? s_bin[idx] : 0;
            local[j] = sum; sum += v;
        }
        int incl = sum;
        #pragma unroll
        for (int off = 1; off < 32; off <<= 1) {
            const int n = __shfl_up_sync(0xFFFFFFFFu, incl, off);
            if (tid >= off) incl += n;
        }
        const int excl = incl - sum;
        #pragma unroll
        for (int j = 0; j < 9; j++) {
            const int idx = tid * 9 + j;
            if (idx < NBIN) s_bin[idx] = excl + local[j];
        }
        if (tid == 31) s_total = incl;
    }
    __syncthreads();                               // scan + s_total

    // ---- scatter (within-tie order result-invariant) + pad ----
    #pragma unroll
    for (int k = 0; k < 5; k++) {
        const int i = tid + k * TPB;
        if (i < SIDE * SIDE) {
            const int dy = i / SIDE - RMAX, dx = i % SIDE - RMAX;
            const int d2 = dy * dy + dx * dx;
            if (d2 <= D2MAX) {
                const int pos = atomicAdd(&s_bin[d2], 1);
                s_tab[pos] = make_int2(dy * TW + dx, __float_as_int((float)d2));
            }
        }
    }
    for (int i = s_total + tid; i < NOFF_CAP; i += TPB)
        s_tab[i] = make_int2(0, 0);
    __syncthreads();                               // table ready

    // ---- final mass: fixed-order sum of 8 warp sums ----
    float mass = 0.0f;
    #pragma unroll
    for (int wi = 0; wi < TPB / 32; wi++) mass += s_wsum[wi];
    const float mt = 0.01f * mass;

    // ---- walk: LDS-only, chunk fast path, divergent break ----
    const int p = blockIdx.x * TPB + tid;
    const int x = p & 63;
    const int tbase = ((tid >> 6) + RMAX) * TW + (x + RMAX);

    float cum = 0.0f, ws = 0.0f;
    for (int i0 = 0; i0 < NOFF_CAP; i0 += CHUNK) {
        if (cum >= mt) break;                      // body runs only if cum < mt

        float w[CHUNK], dv[CHUNK];
        #pragma unroll
        for (int j = 0; j < CHUNK; j++) {
            const int2 e = s_tab[i0 + j];          // broadcast LDS.64
            w[j]  = s_tile[tbase + e.x];           // conflict-free LDS.32
            dv[j] = __int_as_float(e.y);
        }

        const float sum = ((w[0] + w[1]) + (w[2] + w[3]))
                        + ((w[4] + w[5]) + (w[6] + w[7]));
        if (cum + sum <= mt) {
            ws += ((w[0] * dv[0] + w[1] * dv[1]) + (w[2] * dv[2] + w[3] * dv[3]))
                + ((w[4] * dv[4] + w[5] * dv[5]) + (w[6] * dv[6] + w[7] * dv[7]));
        } else {
            float c = cum;                         // crossing chunk: exact clamp
            #pragma unroll
            for (int j = 0; j < CHUNK; j++) {
                const float rem = mt - c;
                ws += fmaxf(fminf(w[j], rem), 0.0f) * dv[j];
                c  += w[j];
            }
        }
        cum += sum;
    }

    out[b * NPIX + p] = (mass == 0.0f) ? 0.0f : sqrtf(ws / mt);
}

extern "C" void kernel_launch(void* const* d_in, const int* in_sizes, int n_in,
                              void* d_out, int out_size) {
    const float* img = (const float*)d_in[0];
    float* out = (float*)d_out;
    dtm_kernel<<<dim3(BLOCKS_PER_B, BATCH), TPB>>>(img, out);
}

// round 11
// speedup vs baseline: 1.4914x; 1.3491x over previous
#include <cuda_runtime.h>
#include <cuda_bf16.h>
#include <math.h>

// ExactWeightedDTM — images (4,1,64,64) f32 -> dtm (4,64,64) f32.
// R=2 => dists_pow == integer d2; crossing always within d2 <= 256 (verified
// rounds 1/3/5/7, rel_err ~1.1e-7). Per pixel: walk offsets ascending d2,
// ws += clamp(w, mt - cum, 0)*d2, cum += w, stop at cum >= mt; dtm=sqrt(ws/mt).
//
// Round 10: compile-time offset table, accessed ONLY with template-parameter
// indices inside a template-recursive fully-unrolled walk, so every table
// read is a front-end constant expression -> immediates in SASS (LDS with
// immediate offset, FFMA-imm). No host-variable-in-device-code (round 9's
// compile error), no materialized __device__ symbol (round 2's init risk),
// no shared-memory table build (rounds 3/5/7's atomics+scan+scatter).

#define H 64
#define W 64
#define NPIX 4096
#define BATCH 4
#define RMAX 16
#define D2MAX 256
#define NOFF_CAP 800       // >= 797 entries; pads {off=0,d2=0} contribute 0
#define CHUNK 8
#define TPB 256
#define ROWS_PB 4
#define BLOCKS_PER_B (H / ROWS_PB)   // 16
#define TW 96              // W + 2*RMAX
#define TH 36              // ROWS_PB + 2*RMAX
#define NTILE (TH * TW)    // 3456 floats
#define NT4 (NTILE / 4)    // 864 float4
#define NV4 (TH * (W / 4)) // 576 interior float4 (36 rows x 16)

struct OffTab { int off[NOFF_CAP]; float d2[NOFF_CAP]; };

__host__ __device__ static constexpr OffTab make_tab() {
    OffTab t{};
    int n = 0;
    for (int d = 0; d <= D2MAX; d++)
        for (int dy = -RMAX; dy <= RMAX; dy++)
            for (int dx = -RMAX; dx <= RMAX; dx++)
                if (dy * dy + dx * dx == d) {
                    t.off[n] = dy * TW + dx;
                    t.d2[n]  = (float)d;
                    n++;
                }
    for (; n < NOFF_CAP; n++) { t.off[n] = 0; t.d2[n] = 0.0f; }
    return t;
}
__device__ constexpr OffTab TAB = make_tab();

// Fully-unrolled walk: one template instantiation per chunk; all table reads
// are constant expressions (template-parameter indices) -> immediates.
template <int I0>
__device__ __forceinline__ void walk_from(const float* __restrict__ tile,
                                          int tbase, float mt,
                                          float& cum, float& ws)
{
    if constexpr (I0 < NOFF_CAP) {
        if (cum >= mt) return;

        constexpr int oo0 = TAB.off[I0 + 0], oo1 = TAB.off[I0 + 1];
        constexpr int oo2 = TAB.off[I0 + 2], oo3 = TAB.off[I0 + 3];
        constexpr int oo4 = TAB.off[I0 + 4], oo5 = TAB.off[I0 + 5];
        constexpr int oo6 = TAB.off[I0 + 6], oo7 = TAB.off[I0 + 7];
        constexpr float e0 = TAB.d2[I0 + 0], e1 = TAB.d2[I0 + 1];
        constexpr float e2 = TAB.d2[I0 + 2], e3 = TAB.d2[I0 + 3];
        constexpr float e4 = TAB.d2[I0 + 4], e5 = TAB.d2[I0 + 5];
        constexpr float e6 = TAB.d2[I0 + 6], e7 = TAB.d2[I0 + 7];

        const float w0 = tile[tbase + oo0], w1 = tile[tbase + oo1];
        const float w2 = tile[tbase + oo2], w3 = tile[tbase + oo3];
        const float w4 = tile[tbase + oo4], w5 = tile[tbase + oo5];
        const float w6 = tile[tbase + oo6], w7 = tile[tbase + oo7];

        const float sum = ((w0 + w1) + (w2 + w3)) + ((w4 + w5) + (w6 + w7));

        if (cum + sum <= mt) {
            ws += ((w0 * e0 + w1 * e1) + (w2 * e2 + w3 * e3))
                + ((w4 * e4 + w5 * e5) + (w6 * e6 + w7 * e7));
        } else {
            // crossing chunk: exact serial clamp (runs once per thread)
            float c = cum, rem;
            rem = mt - c; ws += fmaxf(fminf(w0, rem), 0.0f) * e0; c += w0;
            rem = mt - c; ws += fmaxf(fminf(w1, rem), 0.0f) * e1; c += w1;
            rem = mt - c; ws += fmaxf(fminf(w2, rem), 0.0f) * e2; c += w2;
            rem = mt - c; ws += fmaxf(fminf(w3, rem), 0.0f) * e3; c += w3;
            rem = mt - c; ws += fmaxf(fminf(w4, rem), 0.0f) * e4; c += w4;
            rem = mt - c; ws += fmaxf(fminf(w5, rem), 0.0f) * e5; c += w5;
            rem = mt - c; ws += fmaxf(fminf(w6, rem), 0.0f) * e6; c += w6;
            rem = mt - c; ws += fmaxf(fminf(w7, rem), 0.0f) * e7; c += w7;
        }
        cum += sum;

        walk_from<I0 + CHUNK>(tile, tbase, mt, cum, ws);
    }
}

__global__ void __launch_bounds__(TPB) dtm_kernel(
    const float* __restrict__ img, float* __restrict__ out)
{
    __shared__ float s_tile[NTILE];
    __shared__ float s_wsum[TPB / 32];

    const int tid   = threadIdx.x;
    const int b     = blockIdx.y;
    const float* __restrict__ im = img + b * NPIX;
    const int ybase = blockIdx.x * ROWS_PB - RMAX;

    // ---- issue ALL global loads up front (batched) ----
    float4 m0, m1, m2, m3;
    {
        const float4* __restrict__ im4 = reinterpret_cast<const float4*>(im);
        m0 = im4[tid];       m1 = im4[tid + 256];
        m2 = im4[tid + 512]; m3 = im4[tid + 768];
    }
    // interior tile rows as float4 (row-predicated; 3 per thread)
    float4 tvv[3];
    #pragma unroll
    for (int k = 0; k < 3; k++) {
        const int i  = tid + k * TPB;           // < 768, NV4 = 576
        const int r  = i >> 4;                  // tile row
        const int q  = i & 15;                  // float4 index within row
        const int gy = ybase + r;
        const bool ok = (i < NV4) & ((unsigned)gy < (unsigned)H);
        tvv[k] = ok ? __ldg(reinterpret_cast<const float4*>(im) + (gy << 4) + q)
                    : make_float4(0.f, 0.f, 0.f, 0.f);
    }

    // ---- zero padded tile with STS.128 while loads fly ----
    {
        float4* t4 = reinterpret_cast<float4*>(s_tile);
        #pragma unroll
        for (int k = 0; k < 4; k++) {
            const int i = tid + k * TPB;
            if (i < NT4) t4[i] = make_float4(0.f, 0.f, 0.f, 0.f);
        }
    }
    __syncthreads();                            // zeroing complete

    // ---- store interior (overwrites zeros); offsets 16B-aligned ----
    #pragma unroll
    for (int k = 0; k < 3; k++) {
        const int i = tid + k * TPB;
        const int r = i >> 4, q = i & 15;
        if (i < NV4)
            *reinterpret_cast<float4*>(&s_tile[r * TW + RMAX + (q << 2)]) = tvv[k];
    }

    // ---- mass: fixed deterministic order (identical in every block) ----
    float s = (((m0.x + m0.y) + (m0.z + m0.w)) + ((m1.x + m1.y) + (m1.z + m1.w)))
            + (((m2.x + m2.y) + (m2.z + m2.w)) + ((m3.x + m3.y) + (m3.z + m3.w)));
    #pragma unroll
    for (int o = 16; o > 0; o >>= 1) s += __shfl_xor_sync(0xFFFFFFFFu, s, o);
    if ((tid & 31) == 0) s_wsum[tid >> 5] = s;
    __syncthreads();                            // tile + warp sums ready

    float mass = 0.0f;
    #pragma unroll
    for (int wi = 0; wi < TPB / 32; wi++) mass += s_wsum[wi];
    const float mt = 0.01f * mass;

    // ---- walk: immediate-offset LDS, fully unrolled with early exit ----
    const int p = blockIdx.x * TPB + tid;
    const int x = p & 63;
    const int tbase = ((tid >> 6) + RMAX) * TW + (x + RMAX);

    float cum = 0.0f, ws = 0.0f;
    walk_from<0>(s_tile, tbase, mt, cum, ws);

    out[b * NPIX + p] = (mass == 0.0f) ? 0.0f : sqrtf(ws / mt);
}

extern "C" void kernel_launch(void* const* d_in, const int* in_sizes, int n_in,
                              void* d_out, int out_size) {
    const float* img = (const float*)d_in[0];
    float* out = (float*)d_out;
    dtm_kernel<<<dim3(BLOCKS_PER_B, BATCH), TPB>>>(img, out);
}